// round 2
// baseline (speedup 1.0000x reference)
#include <cuda_runtime.h>

// XrayTransforms: standardize -> soft-hist equalize -> 2x bilinear (=2x2 avg) -> normalize
// x: (2,1,512,512) f32, out: (2,1,256,256) f32
//
// Strategy:
//   k_hist accumulates 3 moments (1, u, u^2) per pixel into 2048 fine sub-bins
//   (3 shared atomics/px instead of 25). A Taylor expansion of the Gaussian
//   around the sub-bin center reconstructs the exact 256-bin soft histogram
//   in k_post (error ~1e-5). Equalize is then tabulated on an 8192-point grid
//   so k_out is a pure lerp.

#define NB 256
#define HW 512
#define NPIX (HW*HW)            // 262144 per batch
#define SUBN 2048               // sub-bin planes length (indices 0..2040 used)
#define SUBSCALE 2040.0f        // v * SUBSCALE = sub-bin position (8 per bin)
#define MRAD 100                // conv radius in sub-bins (12.5 bins)
#define ALPHA 1.2014610918e-3f  // A / 2040^2, A = 5000
#define EXPM2A 0.99759997f      // exp(-2*ALPHA)
#define TABN 8192
#define HBLK 128                // hist blocks per batch
#define RADIUS 12
// A = 1/(2*tau^2) = 5000, Delta = 1/255
#define TWO_A_D  39.21568627450980f   // 2*A*Delta
#define A_D2     0.07689350249903883f // A*Delta^2
#define RATIO_C  0.85745500f          // exp(-2*A*Delta^2)
#define INV255   (1.0f/255.0f)

__device__ int   g_min_bits;
__device__ int   g_max_bits;
__device__ float g_part[2][HBLK][3*SUBN];  // per-block moment partials
__device__ float g_mom[2][3*SUBN];         // reduced moments
__device__ float g_cdfn[2][NB];
__device__ float g_eqtab[2][TABN];

__global__ void k_init() {
    g_min_bits = 0x7f800000;
    g_max_bits = 0;
}

__global__ void k_minmax(const float* __restrict__ x) {
    const float4* x4 = (const float4*)x;
    int n4 = (2 * NPIX) / 4;
    float mn = 1e30f, mx = -1e30f;
    for (int i = blockIdx.x * blockDim.x + threadIdx.x; i < n4; i += gridDim.x * blockDim.x) {
        float4 v = x4[i];
        mn = fminf(mn, fminf(fminf(v.x, v.y), fminf(v.z, v.w)));
        mx = fmaxf(mx, fmaxf(fmaxf(v.x, v.y), fmaxf(v.z, v.w)));
    }
    #pragma unroll
    for (int o = 16; o; o >>= 1) {
        mn = fminf(mn, __shfl_xor_sync(0xFFFFFFFFu, mn, o));
        mx = fmaxf(mx, __shfl_xor_sync(0xFFFFFFFFu, mx, o));
    }
    if ((threadIdx.x & 31) == 0) {
        atomicMin(&g_min_bits, __float_as_int(mn));  // inputs >= 0: int order == float order
        atomicMax(&g_max_bits, __float_as_int(mx));
    }
}

// 3 moment atomics per pixel into fine sub-bins.
__global__ void k_hist(const float* __restrict__ x) {
    __shared__ float sh[3 * SUBN];   // 24KB: [count | u | u^2]
    const int b = blockIdx.y;
    for (int i = threadIdx.x; i < 3 * SUBN; i += blockDim.x) sh[i] = 0.0f;
    __syncthreads();

    const float mn  = __int_as_float(g_min_bits);
    const float inv = 1.0f / (__int_as_float(g_max_bits) - mn + 1e-6f);
    const float4* xb = (const float4*)(x + b * NPIX);
    const int n4 = NPIX / 4;
    const int stride = gridDim.x * blockDim.x;

    for (int idx = blockIdx.x * blockDim.x + threadIdx.x; idx < n4; idx += stride) {
        float4 p4 = xb[idx];
        float vv[4] = {p4.x, p4.y, p4.z, p4.w};
        #pragma unroll
        for (int q = 0; q < 4; q++) {
            float v = (vv[q] - mn) * inv;
            float t = v * SUBSCALE;
            int   i = __float2int_rn(t);
            float u = t - (float)i;       // in [-0.5, 0.5] sub-bin units
            atomicAdd(&sh[i],            1.0f);
            atomicAdd(&sh[SUBN + i],     u);
            atomicAdd(&sh[2*SUBN + i],   u * u);
        }
    }
    __syncthreads();
    float* dst = g_part[b][blockIdx.x];
    for (int i = threadIdx.x; i < 3 * SUBN; i += blockDim.x) dst[i] = sh[i];
}

__global__ void k_reduce() {
    int t = blockIdx.x * blockDim.x + threadIdx.x;   // 12288 threads
    int b = t / (3 * SUBN);
    int e = t % (3 * SUBN);
    float s = 0.0f;
    #pragma unroll 4
    for (int k = 0; k < HBLK; k++) s += g_part[b][k][e];
    g_mom[b][e] = s;
}

// moments -> hist (Taylor conv) -> cdf -> cdfn
__global__ void k_post() {
    __shared__ float s_m[3 * SUBN];   // 24KB
    __shared__ float s_scan[NB];
    const int b = blockIdx.x;
    const int j = threadIdx.x;        // 256 threads = 256 bins
    for (int i = j; i < 3 * SUBN; i += NB) s_m[i] = g_mom[b][i];
    __syncthreads();

    // hist_j = sum_m exp(-ALPHA*m^2) * (M0 - 2*ALPHA*m*M1 + ALPHA*(2*ALPHA*m^2 - 1)*M2)
    int mlo = -MRAD; if (8 * j + mlo < 0)    mlo = -8 * j;
    int mhi =  MRAD; if (8 * j + mhi > 2040) mhi = 2040 - 8 * j;
    float fm = (float)mlo;
    float w  = __expf(-ALPHA * fm * fm);
    float r  = __expf(-ALPHA * (2.0f * fm + 1.0f));
    float h  = 0.0f;
    int i = 8 * j + mlo;
    for (int m = mlo; m <= mhi; m++, i++) {
        float m0 = s_m[i];
        float m1 = s_m[SUBN + i];
        float m2 = s_m[2*SUBN + i];
        float a1 = -2.0f * ALPHA * fm;
        float a2 = ALPHA * (2.0f * ALPHA * fm * fm - 1.0f);
        h += w * (m0 + a1 * m1 + a2 * m2);
        w *= r;
        r *= EXPM2A;
        fm += 1.0f;
    }

    s_scan[j] = h;
    __syncthreads();
    #pragma unroll
    for (int o = 1; o < NB; o <<= 1) {
        float add = (j >= o) ? s_scan[j - o] : 0.0f;
        __syncthreads();
        s_scan[j] += add;
        __syncthreads();
    }
    float total = s_scan[NB - 1];
    float invS  = 1.0f / (total + 1e-10f);
    float cdf   = s_scan[j] * invS;
    float cdf0  = s_scan[0] * invS;
    g_cdfn[b][j] = (cdf - cdf0) / (1.0f - cdf0 + 1e-10f);
}

// Tabulate eq(v) on TABN grid points over v in [0,1].
__global__ void k_table() {
    __shared__ float cdfn[NB];
    const int b = blockIdx.y;
    for (int i = threadIdx.x; i < NB; i += blockDim.x) cdfn[i] = g_cdfn[b][i];
    __syncthreads();

    int p = blockIdx.x * blockDim.x + threadIdx.x;   // 0..TABN-1
    float v = (float)p * (1.0f / (float)(TABN - 1));
    int k = __float2int_rn(v * 255.0f);
    int jlo = k - RADIUS;
    float d0 = v - (float)jlo * INV255;
    float w = __expf(-5000.0f * d0 * d0);
    float r = __expf(TWO_A_D * d0 - A_D2);
    float num = 0.0f, den = 0.0f;
    #pragma unroll
    for (int s = 0; s < 2 * RADIUS + 1; s++) {
        int j = jlo + s;
        if (j >= 0 && j < NB) {
            num += w * cdfn[j];
            den += w;
        }
        w *= r;
        r *= RATIO_C;
    }
    g_eqtab[b][p] = num / (den + 1e-10f);
}

__device__ __forceinline__ float eq_lerp(float xraw, float mn, float inv,
                                         const float* __restrict__ tb) {
    float v = (xraw - mn) * inv;
    float t = v * (float)(TABN - 1);
    int i0 = (int)t;
    float f = t - (float)i0;
    float e0 = __ldg(tb + i0);
    float e1 = __ldg(tb + i0 + 1);
    return fmaf(f, e1 - e0, e0);
}

__global__ void k_out(const float* __restrict__ x, float* __restrict__ out) {
    int idx = blockIdx.x * blockDim.x + threadIdx.x;   // 131072 output pixels
    int b = idx >> 16;
    int rem = idx & 0xFFFF;
    int oy = rem >> 8;
    int ox = rem & 255;
    const float* base = x + b * NPIX;
    float2 t0 = ((const float2*)(base + (2 * oy)     * HW))[ox];
    float2 t1 = ((const float2*)(base + (2 * oy + 1) * HW))[ox];

    const float mn  = __int_as_float(g_min_bits);
    const float inv = 1.0f / (__int_as_float(g_max_bits) - mn + 1e-6f);
    const float* tb = g_eqtab[b];
    float e = eq_lerp(t0.x, mn, inv, tb)
            + eq_lerp(t0.y, mn, inv, tb)
            + eq_lerp(t1.x, mn, inv, tb)
            + eq_lerp(t1.y, mn, inv, tb);
    out[idx] = (0.25f * e - 0.15f) / 0.1f;
}

extern "C" void kernel_launch(void* const* d_in, const int* in_sizes, int n_in,
                              void* d_out, int out_size) {
    const float* x = (const float*)d_in[0];
    float* out = (float*)d_out;
    k_init<<<1, 1>>>();
    k_minmax<<<256, 256>>>(x);
    k_hist<<<dim3(HBLK, 2), 256>>>(x);
    k_reduce<<<48, 256>>>();
    k_post<<<2, NB>>>();
    k_table<<<dim3(TABN / 256, 2), 256>>>();
    k_out<<<512, 256>>>(x, out);
}